// round 5
// baseline (speedup 1.0000x reference)
#include <cuda_runtime.h>
#include <cuda_bf16.h>
#include <cstdint>

// ============================================================================
// out[8192,4096] = fp8_q(x) @ fp8_q(w)^T + bias ; amax EMA scalars at tail.
// sm_103 base ISA: fp8 QMMA path — mma.sync.m16n8k32.f32.e4m3.e4m3.f32.
// ============================================================================

#define FP8_MAX   448.0f
#define AMAX_EPS  1e-8f
#define MOMENTUM  0.95f

static constexpr int M_DIM = 8192;
static constexpr int N_DIM = 4096;
static constexpr int K_DIM = 4096;

static constexpr int BM = 128;
static constexpr int BN = 128;
static constexpr int BK = 128;                   // fp8 elems -> 128B rows
static constexpr int STAGES = 3;
static constexpr int KITERS = K_DIM / BK;        // 32

static constexpr int STAGE_A = BM * BK;          // 16384 B
static constexpr int STAGE_B = BN * BK;          // 16384 B
static constexpr int SMEM_BYTES = STAGES * (STAGE_A + STAGE_B);  // 98304

// Scratch: fp8 bytes
__device__ uint8_t g_xq[(size_t)M_DIM * K_DIM];   // 32 MB
__device__ uint8_t g_wq[(size_t)N_DIM * K_DIM];   // 16 MB
__device__ float g_amax[2];

// ============================================================================
// helpers
// ============================================================================
__device__ __forceinline__ uint32_t smem_u32(const void* p) {
    uint32_t a;
    asm("{ .reg .u64 t; cvta.to.shared.u64 t, %1; cvt.u32.u64 %0, t; }"
        : "=r"(a) : "l"(p));
    return a;
}

__device__ __forceinline__ void cp16(uint32_t dst, const void* src) {
    asm volatile("cp.async.cg.shared.global [%0], [%1], 16;"
                 :: "r"(dst), "l"(src) : "memory");
}

__device__ __forceinline__ void ldmatrix_x4(uint32_t* r, uint32_t addr) {
    asm volatile("ldmatrix.sync.aligned.m8n8.x4.shared.b16 {%0,%1,%2,%3}, [%4];"
                 : "=r"(r[0]), "=r"(r[1]), "=r"(r[2]), "=r"(r[3]) : "r"(addr));
}

// fp8 e4m3 MMA, m16n8k32, fp32 accumulate
__device__ __forceinline__ void mma_fp8(float* c, const uint32_t* a, const uint32_t* b) {
    asm volatile(
        "mma.sync.aligned.m16n8k32.row.col.f32.e4m3.e4m3.f32 "
        "{%0,%1,%2,%3}, {%4,%5,%6,%7}, {%8,%9}, {%0,%1,%2,%3};"
        : "+f"(c[0]), "+f"(c[1]), "+f"(c[2]), "+f"(c[3])
        : "r"(a[0]), "r"(a[1]), "r"(a[2]), "r"(a[3]), "r"(b[0]), "r"(b[1]));
}

// ============================================================================
// small kernels
// ============================================================================
__global__ void init_kernel() { g_amax[0] = 0.0f; g_amax[1] = 0.0f; }

// fp32 -> e4m3 bytes (scaled, satfinite == clip+cast); block-reduced abs-max.
__global__ void __launch_bounds__(256) quant_kernel(
    const float* __restrict__ src, const float* __restrict__ amax_buf,
    int which, int n16)
{
    uint8_t* dst = which ? g_wq : g_xq;
    float* gm = &g_amax[which];

    const int i = blockIdx.x * blockDim.x + threadIdx.x;
    const float scale = FP8_MAX / fmaxf(*amax_buf, AMAX_EPS);

    float m = 0.0f;
    if (i < n16) {
        const float4* s4 = reinterpret_cast<const float4*>(src) + (size_t)i * 4;
        uint32_t w[4];
        #pragma unroll
        for (int j = 0; j < 4; j++) {
            float4 v = s4[j];
            m = fmaxf(m, fmaxf(fmaxf(fabsf(v.x), fabsf(v.y)),
                               fmaxf(fabsf(v.z), fabsf(v.w))));
            float a0 = v.x * scale, a1 = v.y * scale;
            float a2 = v.z * scale, a3 = v.w * scale;
            unsigned short p0, p1;
            asm("cvt.rn.satfinite.e4m3x2.f32 %0, %1, %2;" : "=h"(p0) : "f"(a1), "f"(a0));
            asm("cvt.rn.satfinite.e4m3x2.f32 %0, %1, %2;" : "=h"(p1) : "f"(a3), "f"(a2));
            w[j] = (uint32_t)p0 | ((uint32_t)p1 << 16);
        }
        reinterpret_cast<uint4*>(dst)[i] = make_uint4(w[0], w[1], w[2], w[3]);
    }

    #pragma unroll
    for (int off = 16; off; off >>= 1)
        m = fmaxf(m, __shfl_xor_sync(0xFFFFFFFFu, m, off));
    __shared__ float wmax[8];
    const int wid = threadIdx.x >> 5, lid = threadIdx.x & 31;
    if (lid == 0) wmax[wid] = m;
    __syncthreads();
    if (wid == 0) {
        float mm = (lid < 8) ? wmax[lid] : 0.0f;
        #pragma unroll
        for (int off = 4; off; off >>= 1)
            mm = fmaxf(mm, __shfl_xor_sync(0xFFFFFFFFu, mm, off));
        if (lid == 0)
            atomicMax(reinterpret_cast<int*>(gm), __float_as_int(mm));
    }
}

__global__ void finalize_kernel(const float* __restrict__ ia,
                                const float* __restrict__ wa,
                                float* __restrict__ out_tail)
{
    out_tail[0] = fmaxf(fmaxf(*ia * MOMENTUM, g_amax[0]), AMAX_EPS);
    out_tail[1] = fmaxf(fmaxf(*wa * MOMENTUM, g_amax[1]), AMAX_EPS);
}

// ============================================================================
// GEMM: CTA 128x128x128(fp8), 8 warps (2x4), warp tile 64x32, fp8 QMMA
// smem rows: 128 bytes, swizzle 16B-granularity
// ============================================================================
__global__ void __launch_bounds__(256)
gemm_kernel(const float* __restrict__ bias,
            const float* __restrict__ ia, const float* __restrict__ wa,
            float* __restrict__ out)
{
    extern __shared__ char smem[];
    const uint32_t sbase = smem_u32(smem);

    // L2-friendly rasterization: group 16 m-tiles
    constexpr int NT = N_DIM / BN;   // 32
    constexpr int G = 16;
    const int linear = blockIdx.x;
    const int group = linear / (G * NT);
    const int rem   = linear % (G * NT);
    const int mtile = group * G + (rem % G);
    const int ntile = rem / G;

    const int tid = threadIdx.x;
    const int wid = tid >> 5, lane = tid & 31;
    const int warp_m = wid >> 2;          // 0..1 (64 rows)
    const int warp_n = wid & 3;           // 0..3 (32 cols)

    __shared__ float bs[BN];
    if (tid < BN) bs[tid] = bias[ntile * BN + tid];

    const uint8_t* Ag = g_xq + (size_t)mtile * BM * K_DIM;
    const uint8_t* Bg = g_wq + (size_t)ntile * BN * K_DIM;

    // 1024 16B-chunks per 16KB tile, 4 per thread
    auto issue_stage = [&](int kiter, int stage) {
        const int k0 = kiter * BK;
        const uint32_t sA = sbase + stage * STAGE_A;
        const uint32_t sB = sbase + STAGES * STAGE_A + stage * STAGE_B;
        #pragma unroll
        for (int j = 0; j < 4; j++) {
            int idx = tid + j * 256;
            int row = idx >> 3, c16 = idx & 7;
            uint32_t swcol = (c16 * 16) ^ ((row & 7) << 4);
            cp16(sA + row * 128 + swcol, Ag + (size_t)row * K_DIM + k0 + c16 * 16);
        }
        #pragma unroll
        for (int j = 0; j < 4; j++) {
            int idx = tid + j * 256;
            int row = idx >> 3, c16 = idx & 7;
            uint32_t swcol = (c16 * 16) ^ ((row & 7) << 4);
            cp16(sB + row * 128 + swcol, Bg + (size_t)row * K_DIM + k0 + c16 * 16);
        }
        asm volatile("cp.async.commit_group;" ::: "memory");
    };

    float acc[4][4][4];
    #pragma unroll
    for (int i = 0; i < 4; i++)
        #pragma unroll
        for (int j = 0; j < 4; j++)
            #pragma unroll
            for (int e = 0; e < 4; e++) acc[i][j][e] = 0.0f;

    issue_stage(0, 0);
    issue_stage(1, 1);

    // ldmatrix lane->address mapping (tiles are 8 rows x 16 bytes)
    // A x4: lanes 0-15 -> rows 0..15 @ k-lo16B, lanes 16-31 -> rows 0..15 @ k-hi16B
    //   => r0=(m0-7,k0-15) r1=(m8-15,k0-15) r2=(m0-7,k16-31) r3=(m8-15,k16-31) = a0..a3
    const int a_row_l = warp_m * 64 + (lane & 15);
    const uint32_t a_khalf = (lane >> 4) << 4;
    // B x4: lanes0-7 (n0-7,klo), 8-15 (n0-7,khi), 16-23 (n8-15,klo), 24-31 (n8-15,khi)
    //   => r0,r1 = b-pair for n0-7 ; r2,r3 = pair for n8-15
    const int b_row_l = warp_n * 32 + (lane & 7) + ((lane >> 4) << 3);
    const uint32_t b_khalf = ((lane >> 3) & 1) << 4;

    for (int k = 0; k < KITERS; k++) {
        asm volatile("cp.async.wait_group 1;" ::: "memory");
        __syncthreads();

        if (k + 2 < KITERS) issue_stage(k + 2, (k + 2) % STAGES);
        else asm volatile("cp.async.commit_group;" ::: "memory");

        const int stage = k % STAGES;
        const uint32_t sA = sbase + stage * STAGE_A;
        const uint32_t sB = sbase + STAGES * STAGE_A + stage * STAGE_B;

        #pragma unroll
        for (int ks = 0; ks < BK / 32; ks++) {      // 4 k32 chunks per 128B row
            uint32_t afrag[4][4], bfrag[2][4];
            #pragma unroll
            for (int mi = 0; mi < 4; mi++) {
                int row = a_row_l + mi * 16;
                uint32_t col = ks * 32 + a_khalf;
                ldmatrix_x4(afrag[mi], sA + row * 128 + (col ^ ((row & 7) << 4)));
            }
            #pragma unroll
            for (int nh = 0; nh < 2; nh++) {
                int row = b_row_l + nh * 16;
                uint32_t col = ks * 32 + b_khalf;
                ldmatrix_x4(bfrag[nh], sB + row * 128 + (col ^ ((row & 7) << 4)));
            }
            #pragma unroll
            for (int mi = 0; mi < 4; mi++)
                #pragma unroll
                for (int ni = 0; ni < 4; ni++)
                    mma_fp8(acc[mi][ni], afrag[mi], bfrag[ni >> 1] + (ni & 1) * 2);
        }
        __syncthreads();
    }

    // epilogue: descale + bias
    const float inv = (fmaxf(*ia, AMAX_EPS) * (1.0f / FP8_MAX)) *
                      (fmaxf(*wa, AMAX_EPS) * (1.0f / FP8_MAX));
    const int g = lane >> 2, t = lane & 3;
    #pragma unroll
    for (int mi = 0; mi < 4; mi++) {
        #pragma unroll
        for (int ni = 0; ni < 4; ni++) {
            const int col_l = warp_n * 32 + ni * 8 + t * 2;
            const int col = ntile * BN + col_l;
            const float b0 = bs[col_l], b1 = bs[col_l + 1];
            const int r0 = mtile * BM + warp_m * 64 + mi * 16 + g;
            float2 v0, v1;
            v0.x = acc[mi][ni][0] * inv + b0;
            v0.y = acc[mi][ni][1] * inv + b1;
            v1.x = acc[mi][ni][2] * inv + b0;
            v1.y = acc[mi][ni][3] * inv + b1;
            *reinterpret_cast<float2*>(out + (size_t)r0 * N_DIM + col) = v0;
            *reinterpret_cast<float2*>(out + (size_t)(r0 + 8) * N_DIM + col) = v1;
        }
    }
}

// ============================================================================
// launch
// ============================================================================
extern "C" void kernel_launch(void* const* d_in, const int* in_sizes, int n_in,
                              void* d_out, int out_size)
{
    const float* x    = (const float*)d_in[0];
    const float* w    = (const float*)d_in[1];
    const float* bias = (const float*)d_in[2];
    const float* ia   = (const float*)d_in[3];
    const float* wa   = (const float*)d_in[4];
    float* out = (float*)d_out;

    cudaFuncSetAttribute(gemm_kernel,
                         cudaFuncAttributeMaxDynamicSharedMemorySize, SMEM_BYTES);

    init_kernel<<<1, 1>>>();

    const int n16_x = (M_DIM * K_DIM) / 16;
    const int n16_w = (N_DIM * K_DIM) / 16;
    quant_kernel<<<n16_x / 256, 256>>>(x, ia, 0, n16_x);
    quant_kernel<<<n16_w / 256, 256>>>(w, wa, 1, n16_w);

    const int ntiles = (M_DIM / BM) * (N_DIM / BN);   // 2048
    gemm_kernel<<<ntiles, 256, SMEM_BYTES>>>(bias, ia, wa, out);

    finalize_kernel<<<1, 1>>>(ia, wa, out + (size_t)M_DIM * N_DIM);
}

// round 6
// speedup vs baseline: 1.8007x; 1.8007x over previous
#include <cuda_runtime.h>
#include <cuda_bf16.h>
#include <cuda_fp8.h>
#include <cstdint>

// ============================================================================
// out[8192,4096] = fp8_q(x) @ fp8_q(w)^T + bias ; amax EMA scalars at tail.
// sm_103 base ISA: bf16 mma.sync (fp8 mma.sync measured SLOWER on this chip).
// fp8-quantized values are exact in bf16 -> GEMM in bf16, fp32 accum.
// R6: single barrier per k-iter + register double-buffered fragments.
// ============================================================================

#define FP8_MAX   448.0f
#define AMAX_EPS  1e-8f
#define MOMENTUM  0.95f

static constexpr int M_DIM = 8192;
static constexpr int N_DIM = 4096;
static constexpr int K_DIM = 4096;

static constexpr int BM = 128;
static constexpr int BN = 128;
static constexpr int BK = 64;                    // bf16 elems -> 128B rows
static constexpr int STAGES = 3;
static constexpr int KITERS = K_DIM / BK;        // 64

static constexpr int STAGE_A = BM * BK * 2;      // 16384 B
static constexpr int STAGE_B = BN * BK * 2;      // 16384 B
static constexpr int SMEM_BYTES = STAGES * (STAGE_A + STAGE_B);  // 98304

// Scratch: scaled-quantized values stored as bf16 (exact superset of e4m3)
__device__ __nv_bfloat16 g_xb[(size_t)M_DIM * K_DIM];   // 64 MB
__device__ __nv_bfloat16 g_wb[(size_t)N_DIM * K_DIM];   // 32 MB
__device__ float g_amax[2];

// ============================================================================
// helpers
// ============================================================================
__device__ __forceinline__ uint32_t smem_u32(const void* p) {
    uint32_t a;
    asm("{ .reg .u64 t; cvta.to.shared.u64 t, %1; cvt.u32.u64 %0, t; }"
        : "=r"(a) : "l"(p));
    return a;
}

__device__ __forceinline__ void cp16(uint32_t dst, const void* src) {
    asm volatile("cp.async.cg.shared.global [%0], [%1], 16;"
                 :: "r"(dst), "l"(src) : "memory");
}

__device__ __forceinline__ void ldmatrix_x4(uint32_t* r, uint32_t addr) {
    asm volatile("ldmatrix.sync.aligned.m8n8.x4.shared.b16 {%0,%1,%2,%3}, [%4];"
                 : "=r"(r[0]), "=r"(r[1]), "=r"(r[2]), "=r"(r[3]) : "r"(addr));
}

__device__ __forceinline__ void mma_bf16(float* c, const uint32_t* a, const uint32_t* b) {
    asm volatile(
        "mma.sync.aligned.m16n8k16.row.col.f32.bf16.bf16.f32 "
        "{%0,%1,%2,%3}, {%4,%5,%6,%7}, {%8,%9}, {%0,%1,%2,%3};"
        : "+f"(c[0]), "+f"(c[1]), "+f"(c[2]), "+f"(c[3])
        : "r"(a[0]), "r"(a[1]), "r"(a[2]), "r"(a[3]), "r"(b[0]), "r"(b[1]));
}

// ============================================================================
// small kernels
// ============================================================================
__global__ void init_kernel() { g_amax[0] = 0.0f; g_amax[1] = 0.0f; }

// fp32 -> e4m3(RN,satfinite) -> bf16 (exact), scaled; block-reduced abs-max.
__global__ void __launch_bounds__(256) quant_kernel(
    const float* __restrict__ src, const float* __restrict__ amax_buf,
    int which, int n16)
{
    __nv_bfloat16* dst = which ? g_wb : g_xb;
    float* gm = &g_amax[which];

    const int i = blockIdx.x * blockDim.x + threadIdx.x;
    const float scale = FP8_MAX / fmaxf(*amax_buf, AMAX_EPS);

    float m = 0.0f;
    if (i < n16) {
        const float4* s4 = reinterpret_cast<const float4*>(src) + (size_t)i * 4;
        uint32_t outw[8];
        #pragma unroll
        for (int j = 0; j < 4; j++) {
            float4 v = s4[j];
            m = fmaxf(m, fmaxf(fmaxf(fabsf(v.x), fabsf(v.y)),
                               fmaxf(fabsf(v.z), fabsf(v.w))));
            float f[4];
            f[0] = v.x * scale; f[1] = v.y * scale;
            f[2] = v.z * scale; f[3] = v.w * scale;
            unsigned short us[4];
            #pragma unroll
            for (int e = 0; e < 4; e++) {
                __nv_fp8_e4m3 q;
                q.__x = __nv_cvt_float_to_fp8(f[e], __NV_SATFINITE, __NV_E4M3);
                us[e] = __bfloat16_as_ushort(__float2bfloat16(float(q)));
            }
            outw[j * 2 + 0] = (uint32_t)us[0] | ((uint32_t)us[1] << 16);
            outw[j * 2 + 1] = (uint32_t)us[2] | ((uint32_t)us[3] << 16);
        }
        uint4* d4 = reinterpret_cast<uint4*>(dst) + (size_t)i * 2;
        d4[0] = make_uint4(outw[0], outw[1], outw[2], outw[3]);
        d4[1] = make_uint4(outw[4], outw[5], outw[6], outw[7]);
    }

    #pragma unroll
    for (int off = 16; off; off >>= 1)
        m = fmaxf(m, __shfl_xor_sync(0xFFFFFFFFu, m, off));
    __shared__ float wmax[8];
    const int wid = threadIdx.x >> 5, lid = threadIdx.x & 31;
    if (lid == 0) wmax[wid] = m;
    __syncthreads();
    if (wid == 0) {
        float mm = (lid < 8) ? wmax[lid] : 0.0f;
        #pragma unroll
        for (int off = 4; off; off >>= 1)
            mm = fmaxf(mm, __shfl_xor_sync(0xFFFFFFFFu, mm, off));
        if (lid == 0)
            atomicMax(reinterpret_cast<int*>(gm), __float_as_int(mm));
    }
}

__global__ void finalize_kernel(const float* __restrict__ ia,
                                const float* __restrict__ wa,
                                float* __restrict__ out_tail)
{
    out_tail[0] = fmaxf(fmaxf(*ia * MOMENTUM, g_amax[0]), AMAX_EPS);
    out_tail[1] = fmaxf(fmaxf(*wa * MOMENTUM, g_amax[1]), AMAX_EPS);
}

// ============================================================================
// GEMM: CTA 128x128x64, 8 warps (2x4), warp tile 64x32, mma.sync bf16
// ============================================================================
__global__ void __launch_bounds__(256, 2)
gemm_kernel(const float* __restrict__ bias,
            const float* __restrict__ ia, const float* __restrict__ wa,
            float* __restrict__ out)
{
    extern __shared__ char smem[];
    const uint32_t sbase = smem_u32(smem);

    // L2-friendly rasterization: group 16 m-tiles
    constexpr int NT = N_DIM / BN;   // 32
    constexpr int G = 16;
    const int linear = blockIdx.x;
    const int group = linear / (G * NT);
    const int rem   = linear % (G * NT);
    const int mtile = group * G + (rem % G);
    const int ntile = rem / G;

    const int tid = threadIdx.x;
    const int wid = tid >> 5, lane = tid & 31;
    const int warp_m = wid >> 2;          // 0..1 (64 rows each)
    const int warp_n = wid & 3;           // 0..3 (32 cols each)

    __shared__ float bs[BN];
    if (tid < BN) bs[tid] = bias[ntile * BN + tid];

    const __nv_bfloat16* Ag = g_xb + (size_t)mtile * BM * K_DIM;
    const __nv_bfloat16* Bg = g_wb + (size_t)ntile * BN * K_DIM;

    auto issue_stage = [&](int kiter, int stage) {
        const int k0 = kiter * BK;
        const uint32_t sA = sbase + stage * STAGE_A;
        const uint32_t sB = sbase + STAGES * STAGE_A + stage * STAGE_B;
        #pragma unroll
        for (int j = 0; j < 4; j++) {
            int idx = tid + j * 256;
            int row = idx >> 3, c16 = idx & 7;
            uint32_t swcol = (c16 * 16) ^ ((row & 7) << 4);
            cp16(sA + row * 128 + swcol, Ag + (size_t)row * K_DIM + k0 + c16 * 8);
        }
        #pragma unroll
        for (int j = 0; j < 4; j++) {
            int idx = tid + j * 256;
            int row = idx >> 3, c16 = idx & 7;
            uint32_t swcol = (c16 * 16) ^ ((row & 7) << 4);
            cp16(sB + row * 128 + swcol, Bg + (size_t)row * K_DIM + k0 + c16 * 8);
        }
        asm volatile("cp.async.commit_group;" ::: "memory");
    };

    float acc[4][4][4];
    #pragma unroll
    for (int i = 0; i < 4; i++)
        #pragma unroll
        for (int j = 0; j < 4; j++)
            #pragma unroll
            for (int e = 0; e < 4; e++) acc[i][j][e] = 0.0f;

    // prologue
    issue_stage(0, 0);
    issue_stage(1, 1);

    // ldmatrix lane->address mapping
    // A x4: r0=(m0-7,klo) r1=(m8-15,klo) r2=(m0-7,khi) r3=(m8-15,khi)
    const int a_row_l = warp_m * 64 + (lane & 15);
    const uint32_t a_khalf = (lane >> 4) << 4;      // 0 or 16 bytes
    // B x4: r0,r1 = n0-7 pair ; r2,r3 = n8-15 pair
    const int b_row_l = warp_n * 32 + (lane & 7) + ((lane >> 4) << 3);
    const uint32_t b_khalf = ((lane >> 3) & 1) << 4;

    // double-buffered fragments
    uint32_t afrag[2][4][4], bfrag[2][2][4];

    auto load_frags = [&](int buf, uint32_t sA, uint32_t sB, int ks) {
        #pragma unroll
        for (int mi = 0; mi < 4; mi++) {
            int row = a_row_l + mi * 16;
            uint32_t col = (uint32_t)ks * 32 + a_khalf;
            ldmatrix_x4(afrag[buf][mi], sA + row * 128 + (col ^ ((row & 7) << 4)));
        }
        #pragma unroll
        for (int nh = 0; nh < 2; nh++) {
            int row = b_row_l + nh * 16;
            uint32_t col = (uint32_t)ks * 32 + b_khalf;
            ldmatrix_x4(bfrag[buf][nh], sB + row * 128 + (col ^ ((row & 7) << 4)));
        }
    };

    for (int k = 0; k < KITERS; k++) {
        asm volatile("cp.async.wait_group 1;" ::: "memory");
        __syncthreads();
        // Stage (k+2)%3 was last READ at iter k-1; the sync above already
        // guarantees every warp has finished those reads -> safe to overwrite.
        if (k + 2 < KITERS) issue_stage(k + 2, (k + 2) % STAGES);
        else asm volatile("cp.async.commit_group;" ::: "memory");

        const int stage = k % STAGES;
        const uint32_t sA = sbase + stage * STAGE_A;
        const uint32_t sB = sbase + STAGES * STAGE_A + stage * STAGE_B;

        load_frags(0, sA, sB, 0);
        #pragma unroll
        for (int ks = 0; ks < BK / 16; ks++) {
            const int cur = ks & 1;
            if (ks + 1 < BK / 16) load_frags(cur ^ 1, sA, sB, ks + 1);
            #pragma unroll
            for (int mi = 0; mi < 4; mi++)
                #pragma unroll
                for (int ni = 0; ni < 4; ni++)
                    mma_bf16(acc[mi][ni], afrag[cur][mi],
                             bfrag[cur][ni >> 1] + (ni & 1) * 2);
        }
        // no trailing __syncthreads: next iter's leading barrier covers the
        // read-before-overwrite hazard (stage distance 3 > in-flight distance).
    }

    // epilogue: descale + bias
    const float inv = (fmaxf(*ia, AMAX_EPS) * (1.0f / FP8_MAX)) *
                      (fmaxf(*wa, AMAX_EPS) * (1.0f / FP8_MAX));
    const int g = lane >> 2, t = lane & 3;
    #pragma unroll
    for (int mi = 0; mi < 4; mi++) {
        #pragma unroll
        for (int ni = 0; ni < 4; ni++) {
            const int col_l = warp_n * 32 + ni * 8 + t * 2;
            const int col = ntile * BN + col_l;
            const float b0 = bs[col_l], b1 = bs[col_l + 1];
            const int r0 = mtile * BM + warp_m * 64 + mi * 16 + g;
            float2 v0, v1;
            v0.x = acc[mi][ni][0] * inv + b0;
            v0.y = acc[mi][ni][1] * inv + b1;
            v1.x = acc[mi][ni][2] * inv + b0;
            v1.y = acc[mi][ni][3] * inv + b1;
            *reinterpret_cast<float2*>(out + (size_t)r0 * N_DIM + col) = v0;
            *reinterpret_cast<float2*>(out + (size_t)(r0 + 8) * N_DIM + col) = v1;
        }
    }
}

// ============================================================================
// launch
// ============================================================================
extern "C" void kernel_launch(void* const* d_in, const int* in_sizes, int n_in,
                              void* d_out, int out_size)
{
    const float* x    = (const float*)d_in[0];
    const float* w    = (const float*)d_in[1];
    const float* bias = (const float*)d_in[2];
    const float* ia   = (const float*)d_in[3];
    const float* wa   = (const float*)d_in[4];
    float* out = (float*)d_out;

    cudaFuncSetAttribute(gemm_kernel,
                         cudaFuncAttributeMaxDynamicSharedMemorySize, SMEM_BYTES);

    init_kernel<<<1, 1>>>();

    const int n16_x = (M_DIM * K_DIM) / 16;
    const int n16_w = (N_DIM * K_DIM) / 16;
    quant_kernel<<<n16_x / 256, 256>>>(x, ia, 0, n16_x);
    quant_kernel<<<n16_w / 256, 256>>>(w, wa, 1, n16_w);

    const int ntiles = (M_DIM / BM) * (N_DIM / BN);   // 2048
    gemm_kernel<<<ntiles, 256, SMEM_BYTES>>>(bias, ia, wa, out);

    finalize_kernel<<<1, 1>>>(ia, wa, out + (size_t)M_DIM * N_DIM);
}